// round 6
// baseline (speedup 1.0000x reference)
#include <cuda_runtime.h>
#include <math.h>

#define BB   128      // batch
#define HH   512      // hidden
#define INDIM 256
#define EDIM 256
#define VV   20000
#define TSRC 64
#define TTRG 50
#define G3H  1536     // 3*H

// ---------------- scratch (device globals; no allocation) ----------------
__device__ float g_h[BB*HH];
__device__ float g_gi_enc[(size_t)TSRC*BB*G3H];   // 50.3 MB
__device__ float g_gi[BB*G3H];
__device__ float g_gh[BB*G3H];
__device__ float g_logits[(size_t)BB*VV];         // 10.24 MB
__device__ int   g_eid[BB];
__device__ float g_rate[BB];

// ---- XLA f32 tanh: Eigen-style rational approximation, no FMA fusion ----
__device__ __forceinline__ float xla_tanh(float x){
    float ax = fabsf(x);
    float xc = fmaxf(-7.90531110763549805f, fminf(7.90531110763549805f, x));
    float x2 = __fmul_rn(xc, xc);
    float np = -2.76076847742355e-16f;
    np = __fadd_rn(__fmul_rn(np, x2),  2.00018790482477e-13f);
    np = __fadd_rn(__fmul_rn(np, x2), -8.60467152213735e-11f);
    np = __fadd_rn(__fmul_rn(np, x2),  5.12229709037114e-08f);
    np = __fadd_rn(__fmul_rn(np, x2),  1.48572235717979e-05f);
    np = __fadd_rn(__fmul_rn(np, x2),  6.37261928875436e-04f);
    np = __fadd_rn(__fmul_rn(np, x2),  4.89352455891786e-03f);
    np = __fmul_rn(np, xc);
    float dp = 1.19825839466702e-06f;
    dp = __fadd_rn(__fmul_rn(dp, x2), 1.18534705686654e-04f);
    dp = __fadd_rn(__fmul_rn(dp, x2), 2.26843463243900e-03f);
    dp = __fadd_rn(__fmul_rn(dp, x2), 4.89352518554385e-03f);
    float r = __fdiv_rn(np, dp);
    return (ax < 0.0004f) ? x : r;
}
// XLA logistic expansion: sigmoid(x) = 0.5 + 0.5*tanh(0.5*x), no FMA
__device__ __forceinline__ float xla_sigmoid(float x){
    return __fadd_rn(0.5f, __fmul_rn(0.5f, xla_tanh(__fmul_rn(0.5f, x))));
}

// ---------------- SGEMM: C[M,N] = Aop[M,K] * W[N,K]^T + bias[N] ------------
// Plain fp32 FMA accumulation (accumulation order proven insensitive).
// AMODE 0: A is a plain row-major [M,lda] matrix
// AMODE 1: A row m is [emb[eid[m]] (256 floats) , rate[m]]  (K must be 257)
template<int BM,int BN,int BK,int TM,int TN,int AMODE>
__global__ void sgemm_k(const float* __restrict__ A, int lda,
                        const float* __restrict__ W,
                        const float* __restrict__ bias,
                        float* __restrict__ C,
                        int M, int N, int K,
                        const int*   __restrict__ eid,
                        const float* __restrict__ rate,
                        const float* __restrict__ emb)
{
    __shared__ float As[BK][BM+4];   // transposed: As[k][m]
    __shared__ float Ws[BK][BN+4];   // transposed: Ws[k][n]
    constexpr int NT = (BM/TM)*(BN/TN);
    const int tx = threadIdx.x;                 // [0, BN/TN)
    const int ty = threadIdx.y;                 // [0, BM/TM)
    const int tid = ty*(BN/TN)+tx;
    const int bm0 = blockIdx.y*BM;
    const int bn0 = blockIdx.x*BN;

    float acc[TM][TN];
    #pragma unroll
    for (int i=0;i<TM;i++)
        #pragma unroll
        for (int j=0;j<TN;j++) acc[i][j]=0.f;

    for (int k0=0;k0<K;k0+=BK){
        // stage A tile (coalesced over k)
        #pragma unroll
        for (int i=tid;i<BM*BK;i+=NT){
            int kl=i%BK, ml=i/BK;
            int m=bm0+ml, kg=k0+kl;
            float v=0.f;
            if constexpr (AMODE==0){
                if (m<M && kg<K) v = A[(size_t)m*lda + kg];
            } else {
                if (kg<K) v = (kg<EDIM) ? emb[(size_t)eid[m]*EDIM + kg] : rate[m];
            }
            As[kl][ml]=v;
        }
        // stage W tile (coalesced over k)
        #pragma unroll
        for (int i=tid;i<BN*BK;i+=NT){
            int kl=i%BK, nl=i/BK;
            int n=bn0+nl, kg=k0+kl;
            float v=0.f;
            if (n<N && kg<K) v = W[(size_t)n*K + kg];
            Ws[kl][nl]=v;
        }
        __syncthreads();
        #pragma unroll
        for (int kk=0;kk<BK;kk++){
            float a[TM], b[TN];
            if constexpr (TM%4==0){
                #pragma unroll
                for (int i=0;i<TM;i+=4){
                    float4 v = *(const float4*)&As[kk][ty*TM+i];
                    a[i]=v.x; a[i+1]=v.y; a[i+2]=v.z; a[i+3]=v.w;
                }
            } else {
                #pragma unroll
                for (int i=0;i<TM;i++) a[i]=As[kk][ty*TM+i];
            }
            if constexpr (TN%4==0){
                #pragma unroll
                for (int j=0;j<TN;j+=4){
                    float4 v = *(const float4*)&Ws[kk][tx*TN+j];
                    b[j]=v.x; b[j+1]=v.y; b[j+2]=v.z; b[j+3]=v.w;
                }
            } else {
                #pragma unroll
                for (int j=0;j<TN;j++) b[j]=Ws[kk][tx*TN+j];
            }
            #pragma unroll
            for (int i=0;i<TM;i++)
                #pragma unroll
                for (int j=0;j<TN;j++)
                    acc[i][j] = fmaf(a[i], b[j], acc[i][j]);
        }
        __syncthreads();
    }
    #pragma unroll
    for (int i=0;i<TM;i++){
        int m=bm0+ty*TM+i;
        if (m>=M) continue;
        #pragma unroll
        for (int j=0;j<TN;j++){
            int n=bn0+tx*TN+j;
            if (n<N) C[(size_t)m*N+n] = __fadd_rn(acc[i][j], bias[n]);
        }
    }
}

// ---------------- GRU gate combine: h = (1-z)*n + z*h  (r,z,n PyTorch order)
// All elementwise math in XLA emission form (no FMA contraction).
__global__ void gate_k(const float* __restrict__ gi, const float* __restrict__ gh,
                       const int* __restrict__ src_len, int t, int masked)
{
    int idx = blockIdx.x*blockDim.x + threadIdx.x;
    if (idx >= BB*HH) return;
    int b = idx / HH, j = idx % HH;
    const float* gib = gi + (size_t)b*G3H;
    const float* ghb = gh + (size_t)b*G3H;
    float r = xla_sigmoid(__fadd_rn(gib[j],      ghb[j]));
    float z = xla_sigmoid(__fadd_rn(gib[HH+j],   ghb[HH+j]));
    float n = xla_tanh(__fadd_rn(gib[2*HH+j], __fmul_rn(r, ghb[2*HH+j])));
    float hp = g_h[idx];
    float hn = __fadd_rn(__fmul_rn(__fsub_rn(1.f, z), n), __fmul_rn(z, hp));
    if (masked && t >= src_len[b]) hn = hp;
    g_h[idx] = hn;
}

// ---------------- per-row logsumexp + logp writeback + argmax(logp) -------
__global__ void softmax_k(float* __restrict__ out, int step)
{
    int b = blockIdx.x, tid = threadIdx.x;
    const float* row = g_logits + (size_t)b*VV;
    __shared__ float sv[256];
    __shared__ int   si[256];
    __shared__ double sd[256];
    // pass 1: row max
    float m = -3.4e38f;
    for (int k=tid;k<VV;k+=256) m = fmaxf(m, row[k]);
    sv[tid]=m; __syncthreads();
    for (int s=128;s>0;s>>=1){ if (tid<s) sv[tid]=fmaxf(sv[tid],sv[tid+s]); __syncthreads(); }
    float mx = sv[0];
    __syncthreads();
    // pass 2: sum(exp(shifted)) — fp32 partials into a double tree
    float ps=0.f;
    double pd=0.0;
    int cnt=0;
    for (int k=tid;k<VV;k+=256){
        ps += expf(__fsub_rn(row[k], mx));
        if (++cnt==16){ pd += (double)ps; ps=0.f; cnt=0; }
    }
    pd += (double)ps;
    sd[tid]=pd; __syncthreads();
    for (int st=128;st>0;st>>=1){ if (tid<st) sd[tid]+=sd[tid+st]; __syncthreads(); }
    float lsh = logf((float)sd[0]);
    // pass 3: write logp in reference rounding order; argmax over written values
    float* o = out + ((size_t)step*BB + b)*VV;
    float bm = -3.4e38f; int bi = VV;
    for (int k=tid;k<VV;k+=256){
        float v = __fsub_rn(__fsub_rn(row[k], mx), lsh);
        o[k] = v;
        if (v>bm || (v==bm && k<bi)){ bm=v; bi=k; }
    }
    sv[tid]=bm; si[tid]=bi; __syncthreads();
    for (int s=128;s>0;s>>=1){
        if (tid<s){
            float v2=sv[tid+s]; int i2=si[tid+s];
            if (v2>sv[tid] || (v2==sv[tid] && i2<si[tid])){ sv[tid]=v2; si[tid]=i2; }
        }
        __syncthreads();
    }
    if (tid==0) g_eid[b] = si[0];
}

// ---------------- rate head: sigmoid( relu([emb[eid],h]@W1^T+b1) @ W2^T + b2 )
__global__ void rate_head_k(const float* __restrict__ W1, const float* __restrict__ b1,
                            const float* __restrict__ W2, const float* __restrict__ b2,
                            const float* __restrict__ emb,
                            float* __restrict__ out_rate, int step)
{
    int b = blockIdx.x, tid = threadIdx.x;
    __shared__ float xc[EDIM+HH];   // 768
    __shared__ double red[256];
    int e = g_eid[b];
    if (tid < EDIM) xc[tid] = emb[(size_t)e*EDIM + tid];
    for (int k=tid;k<HH;k+=256) xc[EDIM+k] = g_h[(size_t)b*HH + k];
    __syncthreads();
    double partial = 0.0;
    for (int j=tid;j<HH;j+=256){
        const float* w = W1 + (size_t)j*(EDIM+HH);
        float acc = 0.f;
        #pragma unroll 8
        for (int k=0;k<EDIM+HH;k+=4){
            float4 wv = *(const float4*)(w+k);
            acc = fmaf(wv.x, xc[k],   acc);
            acc = fmaf(wv.y, xc[k+1], acc);
            acc = fmaf(wv.z, xc[k+2], acc);
            acc = fmaf(wv.w, xc[k+3], acc);
        }
        float pre = __fadd_rn(acc, b1[j]);
        partial += (double)__fmul_rn(fmaxf(pre, 0.f), W2[j]);
    }
    red[tid]=partial; __syncthreads();
    for (int s=128;s>0;s>>=1){ if (tid<s) red[tid]+=red[tid+s]; __syncthreads(); }
    if (tid==0){
        float y = __fadd_rn((float)red[0], b2[0]);
        float pr = xla_sigmoid(y);
        out_rate[step*BB + b] = pr;
        g_rate[b] = pr;
    }
}

// ---------------- init: zero step-0 outputs, h=0, seed decoder carry -------
__global__ void init_k(float* __restrict__ out, const int* __restrict__ trg_eid,
                       const float* __restrict__ trg_rate)
{
    long long i = (long long)blockIdx.x*blockDim.x + threadIdx.x;
    const long long RATE_OFF = (long long)TTRG*BB*VV;
    if (i < (long long)BB*VV) out[i] = 0.f;               // logp step 0
    if (i < BB)               out[RATE_OFF + i] = 0.f;    // rate step 0
    if (i < BB*HH)            g_h[i] = 0.f;
    if (i < BB){ g_eid[i] = trg_eid[i]; g_rate[i] = trg_rate[i]; }
}

// ---------------- launch -----------------------------------------------
extern "C" void kernel_launch(void* const* d_in, const int* in_sizes, int n_in,
                              void* d_out, int out_size)
{
    const float* src      = (const float*)d_in[0];
    const int*   src_len  = (const int*)  d_in[1];
    const int*   trg_eid  = (const int*)  d_in[2];
    const float* trg_rate = (const float*)d_in[3];
    const float* emb      = (const float*)d_in[4];
    const float* enc_Wi   = (const float*)d_in[5];
    const float* enc_Wh   = (const float*)d_in[6];
    const float* enc_bi   = (const float*)d_in[7];
    const float* enc_bh   = (const float*)d_in[8];
    const float* dec_Wi   = (const float*)d_in[9];
    const float* dec_Wh   = (const float*)d_in[10];
    const float* dec_bi   = (const float*)d_in[11];
    const float* dec_bh   = (const float*)d_in[12];
    const float* We       = (const float*)d_in[13];
    const float* be       = (const float*)d_in[14];
    const float* W1       = (const float*)d_in[15];
    const float* b1       = (const float*)d_in[16];
    const float* W2       = (const float*)d_in[17];
    const float* b2       = (const float*)d_in[18];
    float* out = (float*)d_out;

    float *p_gi_enc, *p_gi, *p_gh, *p_logits, *p_h, *p_rate;
    int   *p_eid;
    cudaGetSymbolAddress((void**)&p_gi_enc, g_gi_enc);
    cudaGetSymbolAddress((void**)&p_gi,     g_gi);
    cudaGetSymbolAddress((void**)&p_gh,     g_gh);
    cudaGetSymbolAddress((void**)&p_logits, g_logits);
    cudaGetSymbolAddress((void**)&p_h,      g_h);
    cudaGetSymbolAddress((void**)&p_eid,    g_eid);
    cudaGetSymbolAddress((void**)&p_rate,   g_rate);

    init_k<<<10000,256>>>(out, trg_eid, trg_rate);

    // Encoder: precompute gi for all timesteps in one big parallel GEMM
    sgemm_k<64,64,32,4,4,0><<<dim3(G3H/64, (TSRC*BB)/64), dim3(16,16)>>>(
        src, INDIM, enc_Wi, enc_bi, p_gi_enc, TSRC*BB, G3H, INDIM,
        nullptr, nullptr, nullptr);

    // Encoder recurrence (masked / packed semantics)
    for (int t=0;t<TSRC;t++){
        sgemm_k<32,64,32,2,4,0><<<dim3(G3H/64, BB/32), dim3(16,16)>>>(
            p_h, HH, enc_Wh, enc_bh, p_gh, BB, G3H, HH,
            nullptr, nullptr, nullptr);
        gate_k<<<(BB*HH)/256,256>>>(p_gi_enc + (size_t)t*BB*G3H, p_gh, src_len, t, 1);
    }

    // Decoder: greedy autoregressive
    for (int step=1; step<TTRG; step++){
        sgemm_k<32,64,32,2,4,1><<<dim3(G3H/64, BB/32), dim3(16,16)>>>(
            nullptr, 0, dec_Wi, dec_bi, p_gi, BB, G3H, EDIM+1,
            p_eid, p_rate, emb);
        sgemm_k<32,64,32,2,4,0><<<dim3(G3H/64, BB/32), dim3(16,16)>>>(
            p_h, HH, dec_Wh, dec_bh, p_gh, BB, G3H, HH,
            nullptr, nullptr, nullptr);
        gate_k<<<(BB*HH)/256,256>>>(p_gi, p_gh, nullptr, 0, 0);
        sgemm_k<128,64,32,8,4,0><<<dim3((VV+63)/64, 1), dim3(16,16)>>>(
            p_h, HH, We, be, p_logits, BB, VV, HH,
            nullptr, nullptr, nullptr);
        softmax_k<<<BB,256>>>(out, step);
        rate_head_k<<<BB,256>>>(W1, b1, W2, b2, emb,
                                out + (size_t)TTRG*BB*VV, step);
    }
}

// round 7
// speedup vs baseline: 1.7713x; 1.7713x over previous
#include <cuda_runtime.h>
#include <math.h>

#define BB   128      // batch
#define HH   512      // hidden
#define INDIM 256
#define EDIM 256
#define VV   20000
#define TSRC 64
#define TTRG 50
#define G3H  1536     // 3*H
#define KX   (EDIM+1) // 257

// ---------------- scratch (device globals; no allocation) ----------------
__device__ float g_h [BB*HH];
__device__ float g_h2[BB*HH];
__device__ float g_gi_enc[(size_t)TSRC*BB*G3H];   // 50.3 MB
__device__ float g_logits[(size_t)BB*VV];         // 10.24 MB
__device__ int   g_eid[BB];
__device__ float g_rate[BB];

// ---- XLA f32 tanh: Eigen-style rational approximation, no FMA fusion ----
__device__ __forceinline__ float xla_tanh(float x){
    float ax = fabsf(x);
    float xc = fmaxf(-7.90531110763549805f, fminf(7.90531110763549805f, x));
    float x2 = __fmul_rn(xc, xc);
    float np = -2.76076847742355e-16f;
    np = __fadd_rn(__fmul_rn(np, x2),  2.00018790482477e-13f);
    np = __fadd_rn(__fmul_rn(np, x2), -8.60467152213735e-11f);
    np = __fadd_rn(__fmul_rn(np, x2),  5.12229709037114e-08f);
    np = __fadd_rn(__fmul_rn(np, x2),  1.48572235717979e-05f);
    np = __fadd_rn(__fmul_rn(np, x2),  6.37261928875436e-04f);
    np = __fadd_rn(__fmul_rn(np, x2),  4.89352455891786e-03f);
    np = __fmul_rn(np, xc);
    float dp = 1.19825839466702e-06f;
    dp = __fadd_rn(__fmul_rn(dp, x2), 1.18534705686654e-04f);
    dp = __fadd_rn(__fmul_rn(dp, x2), 2.26843463243900e-03f);
    dp = __fadd_rn(__fmul_rn(dp, x2), 4.89352518554385e-03f);
    float r = __fdiv_rn(np, dp);
    return (ax < 0.0004f) ? x : r;
}
// XLA logistic expansion: sigmoid(x) = 0.5 + 0.5*tanh(0.5*x), no FMA
__device__ __forceinline__ float xla_sigmoid(float x){
    return __fadd_rn(0.5f, __fmul_rn(0.5f, xla_tanh(__fmul_rn(0.5f, x))));
}

// ---- packed f32x2 helpers (sm_103a FFMA2 path; lanes = independent FFMA) --
__device__ __forceinline__ unsigned long long packf2(float lo, float hi){
    unsigned long long r;
    asm("mov.b64 %0, {%1, %2};" : "=l"(r)
        : "r"(__float_as_uint(lo)), "r"(__float_as_uint(hi)));
    return r;
}
__device__ __forceinline__ void unpackf2(unsigned long long v, float& lo, float& hi){
    unsigned int a, b;
    asm("mov.b64 {%0, %1}, %2;" : "=r"(a), "=r"(b) : "l"(v));
    lo = __uint_as_float(a); hi = __uint_as_float(b);
}
__device__ __forceinline__ unsigned long long ffma2(
    unsigned long long a, unsigned long long b, unsigned long long c){
    unsigned long long d;
    asm("fma.rn.f32x2 %0, %1, %2, %3;" : "=l"(d) : "l"(a), "l"(b), "l"(c));
    return d;
}

// ---------------- plain SGEMM (encoder-Wi precompute only) ----------------
template<int BM,int BN,int BK,int TM,int TN>
__global__ void sgemm_k(const float* __restrict__ A, int lda,
                        const float* __restrict__ W,
                        const float* __restrict__ bias,
                        float* __restrict__ C,
                        int M, int N, int K)
{
    __shared__ float As[BK][BM+4];
    __shared__ float Ws[BK][BN+4];
    constexpr int NT = (BM/TM)*(BN/TN);
    const int tx = threadIdx.x;
    const int ty = threadIdx.y;
    const int tid = ty*(BN/TN)+tx;
    const int bm0 = blockIdx.y*BM;
    const int bn0 = blockIdx.x*BN;

    float acc[TM][TN];
    #pragma unroll
    for (int i=0;i<TM;i++)
        #pragma unroll
        for (int j=0;j<TN;j++) acc[i][j]=0.f;

    for (int k0=0;k0<K;k0+=BK){
        for (int i=tid;i<BM*BK;i+=NT){
            int kl=i%BK, ml=i/BK;
            int m=bm0+ml, kg=k0+kl;
            As[kl][ml] = (m<M && kg<K) ? A[(size_t)m*lda + kg] : 0.f;
        }
        for (int i=tid;i<BN*BK;i+=NT){
            int kl=i%BK, nl=i/BK;
            int n=bn0+nl, kg=k0+kl;
            Ws[kl][nl] = (n<N && kg<K) ? W[(size_t)n*K + kg] : 0.f;
        }
        __syncthreads();
        #pragma unroll
        for (int kk=0;kk<BK;kk++){
            float a[TM], b[TN];
            #pragma unroll
            for (int i=0;i<TM;i+=4){
                float4 v = *(const float4*)&As[kk][ty*TM+i];
                a[i]=v.x; a[i+1]=v.y; a[i+2]=v.z; a[i+3]=v.w;
            }
            #pragma unroll
            for (int j=0;j<TN;j+=4){
                float4 v = *(const float4*)&Ws[kk][tx*TN+j];
                b[j]=v.x; b[j+1]=v.y; b[j+2]=v.z; b[j+3]=v.w;
            }
            #pragma unroll
            for (int i=0;i<TM;i++)
                #pragma unroll
                for (int j=0;j<TN;j++)
                    acc[i][j] = fmaf(a[i], b[j], acc[i][j]);
        }
        __syncthreads();
    }
    #pragma unroll
    for (int i=0;i<TM;i++){
        int m=bm0+ty*TM+i;
        if (m>=M) continue;
        #pragma unroll
        for (int j=0;j<TN;j++){
            int n=bn0+tx*TN+j;
            if (n<N) C[(size_t)m*N+n] = __fadd_rn(acc[i][j], bias[n]);
        }
    }
}

// ---------------- vocab GEMM: logits[128,20000] = h[128,512] @ We^T + be ---
// FFMA2 (f32x2) mainloop; per-output k-order identical to scalar version.
__global__ __launch_bounds__(256) void vgemm_k(const float* __restrict__ A,
                                               const float* __restrict__ W,
                                               const float* __restrict__ bias,
                                               float* __restrict__ C)
{
    __shared__ float As[32][132];
    __shared__ float Ws[32][132];
    const int tx = threadIdx.x;        // 0..15 (n)
    const int ty = threadIdx.y;        // 0..15 (m)
    const int tid = ty*16+tx;
    const int bn0 = blockIdx.x*128;

    unsigned long long acc2[8][4];
    #pragma unroll
    for (int i=0;i<8;i++)
        #pragma unroll
        for (int p=0;p<4;p++) acc2[i][p]=0ull;   // (+0.f, +0.f)

    for (int k0=0;k0<HH;k0+=32){
        for (int i=tid;i<128*32;i+=256){
            int kl=i%32, ml=i/32;
            As[kl][ml] = A[(size_t)ml*HH + k0+kl];
        }
        for (int i=tid;i<128*32;i+=256){
            int kl=i%32, nl=i/32;
            int n=bn0+nl;
            Ws[kl][nl] = (n<VV) ? W[(size_t)n*HH + k0+kl] : 0.f;
        }
        __syncthreads();
        #pragma unroll
        for (int kk=0;kk<32;kk++){
            float4 a0 = *(const float4*)&As[kk][ty*8];
            float4 a1 = *(const float4*)&As[kk][ty*8+4];
            float4 b0 = *(const float4*)&Ws[kk][tx*8];
            float4 b1 = *(const float4*)&Ws[kk][tx*8+4];
            unsigned long long A2[8], B2[4];
            A2[0]=packf2(a0.x,a0.x); A2[1]=packf2(a0.y,a0.y);
            A2[2]=packf2(a0.z,a0.z); A2[3]=packf2(a0.w,a0.w);
            A2[4]=packf2(a1.x,a1.x); A2[5]=packf2(a1.y,a1.y);
            A2[6]=packf2(a1.z,a1.z); A2[7]=packf2(a1.w,a1.w);
            B2[0]=packf2(b0.x,b0.y); B2[1]=packf2(b0.z,b0.w);
            B2[2]=packf2(b1.x,b1.y); B2[3]=packf2(b1.z,b1.w);
            #pragma unroll
            for (int i=0;i<8;i++)
                #pragma unroll
                for (int p=0;p<4;p++)
                    acc2[i][p] = ffma2(A2[i], B2[p], acc2[i][p]);
        }
        __syncthreads();
    }
    #pragma unroll
    for (int i=0;i<8;i++){
        int m = ty*8+i;
        #pragma unroll
        for (int p=0;p<4;p++){
            float lo, hi;
            unpackf2(acc2[i][p], lo, hi);
            int n0 = bn0 + tx*8 + p*2;
            if (n0   < VV) C[(size_t)m*VV + n0  ] = __fadd_rn(lo, bias[n0  ]);
            if (n0+1 < VV) C[(size_t)m*VV + n0+1] = __fadd_rn(hi, bias[n0+1]);
        }
    }
}

// ---------------- fused encoder GRU step: gh-GEMM + gate (gi precomputed) --
// grid (HH/32=16, BB/16=8), 256 threads. Thread: j = j0+tx, b = b0+2*ty+{0,1}
__global__ __launch_bounds__(256) void gru_enc_k(
    const float* __restrict__ h_in, float* __restrict__ h_out,
    const float* __restrict__ Wh, const float* __restrict__ bh,
    const float* __restrict__ gi_t,
    const int* __restrict__ src_len, int t)
{
    __shared__ float hs[32][17];
    __shared__ float ws[3][32][33];
    const int tid = threadIdx.x;
    const int tx = tid & 31;
    const int ty = tid >> 5;
    const int j0 = blockIdx.x*32;
    const int b0 = blockIdx.y*16;

    float aH[2][3] = {{0.f,0.f,0.f},{0.f,0.f,0.f}};

    for (int k0=0;k0<HH;k0+=32){
        for (int i=tid;i<16*32;i+=256){
            int bl=i>>5, kl=i&31;
            hs[kl][bl] = h_in[(size_t)(b0+bl)*HH + k0+kl];
        }
        #pragma unroll
        for (int g=0; g<3; g++)
            for (int i=tid;i<32*32;i+=256){
                int jl=i>>5, kl=i&31;
                ws[g][kl][jl] = Wh[(size_t)(g*HH + j0+jl)*HH + k0+kl];
            }
        __syncthreads();
        #pragma unroll
        for (int kk=0;kk<32;kk++){
            float a0 = hs[kk][ty*2], a1 = hs[kk][ty*2+1];
            float wr = ws[0][kk][tx], wz = ws[1][kk][tx], wn = ws[2][kk][tx];
            aH[0][0]=fmaf(a0,wr,aH[0][0]); aH[1][0]=fmaf(a1,wr,aH[1][0]);
            aH[0][1]=fmaf(a0,wz,aH[0][1]); aH[1][1]=fmaf(a1,wz,aH[1][1]);
            aH[0][2]=fmaf(a0,wn,aH[0][2]); aH[1][2]=fmaf(a1,wn,aH[1][2]);
        }
        __syncthreads();
    }
    const int j = j0 + tx;
    const float bhr = bh[j], bhz = bh[HH+j], bhn = bh[2*HH+j];
    #pragma unroll
    for (int bl=0; bl<2; bl++){
        int b = b0 + ty*2 + bl;
        const float* gi = gi_t + (size_t)b*G3H;
        float ghr = __fadd_rn(aH[bl][0], bhr);
        float ghz = __fadd_rn(aH[bl][1], bhz);
        float ghn = __fadd_rn(aH[bl][2], bhn);
        float r = xla_sigmoid(__fadd_rn(gi[j],      ghr));
        float z = xla_sigmoid(__fadd_rn(gi[HH+j],   ghz));
        float n = xla_tanh(__fadd_rn(gi[2*HH+j], __fmul_rn(r, ghn)));
        float hp = h_in[(size_t)b*HH + j];
        float hn = __fadd_rn(__fmul_rn(__fsub_rn(1.f,z),n), __fmul_rn(z,hp));
        if (t >= src_len[b]) hn = hp;
        h_out[(size_t)b*HH + j] = hn;
    }
}

// ---------------- fused decoder GRU step: gi-GEMM + gh-GEMM + gate ---------
__global__ __launch_bounds__(256) void gru_dec_k(
    const float* __restrict__ h_in, float* __restrict__ h_out,
    const float* __restrict__ Wi, const float* __restrict__ bi,
    const float* __restrict__ Wh, const float* __restrict__ bh,
    const float* __restrict__ emb)
{
    __shared__ float xs[32][17];
    __shared__ float ws[3][32][33];
    __shared__ int   seid[16];
    __shared__ float srate[16];
    const int tid = threadIdx.x;
    const int tx = tid & 31;
    const int ty = tid >> 5;
    const int j0 = blockIdx.x*32;
    const int b0 = blockIdx.y*16;

    if (tid < 16){ seid[tid] = g_eid[b0+tid]; srate[tid] = g_rate[b0+tid]; }
    __syncthreads();

    float aI[2][3] = {{0.f,0.f,0.f},{0.f,0.f,0.f}};
    float aH[2][3] = {{0.f,0.f,0.f},{0.f,0.f,0.f}};

    // phase 1: input-gate dots over x = [emb[eid], rate], K = 257
    for (int k0=0;k0<KX;k0+=32){
        for (int i=tid;i<16*32;i+=256){
            int bl=i>>5, kl=i&31;
            int kg=k0+kl;
            float v=0.f;
            if (kg<KX) v = (kg<EDIM) ? emb[(size_t)seid[bl]*EDIM + kg] : srate[bl];
            xs[kl][bl]=v;
        }
        #pragma unroll
        for (int g=0; g<3; g++)
            for (int i=tid;i<32*32;i+=256){
                int jl=i>>5, kl=i&31; int kg=k0+kl;
                ws[g][kl][jl] = (kg<KX) ? Wi[(size_t)(g*HH + j0+jl)*KX + kg] : 0.f;
            }
        __syncthreads();
        #pragma unroll
        for (int kk=0;kk<32;kk++){
            float a0 = xs[kk][ty*2], a1 = xs[kk][ty*2+1];
            float wr = ws[0][kk][tx], wz = ws[1][kk][tx], wn = ws[2][kk][tx];
            aI[0][0]=fmaf(a0,wr,aI[0][0]); aI[1][0]=fmaf(a1,wr,aI[1][0]);
            aI[0][1]=fmaf(a0,wz,aI[0][1]); aI[1][1]=fmaf(a1,wz,aI[1][1]);
            aI[0][2]=fmaf(a0,wn,aI[0][2]); aI[1][2]=fmaf(a1,wn,aI[1][2]);
        }
        __syncthreads();
    }
    // phase 2: hidden-gate dots over h, K = 512
    for (int k0=0;k0<HH;k0+=32){
        for (int i=tid;i<16*32;i+=256){
            int bl=i>>5, kl=i&31;
            xs[kl][bl] = h_in[(size_t)(b0+bl)*HH + k0+kl];
        }
        #pragma unroll
        for (int g=0; g<3; g++)
            for (int i=tid;i<32*32;i+=256){
                int jl=i>>5, kl=i&31;
                ws[g][kl][jl] = Wh[(size_t)(g*HH + j0+jl)*HH + k0+kl];
            }
        __syncthreads();
        #pragma unroll
        for (int kk=0;kk<32;kk++){
            float a0 = xs[kk][ty*2], a1 = xs[kk][ty*2+1];
            float wr = ws[0][kk][tx], wz = ws[1][kk][tx], wn = ws[2][kk][tx];
            aH[0][0]=fmaf(a0,wr,aH[0][0]); aH[1][0]=fmaf(a1,wr,aH[1][0]);
            aH[0][1]=fmaf(a0,wz,aH[0][1]); aH[1][1]=fmaf(a1,wz,aH[1][1]);
            aH[0][2]=fmaf(a0,wn,aH[0][2]); aH[1][2]=fmaf(a1,wn,aH[1][2]);
        }
        __syncthreads();
    }
    const int j = j0 + tx;
    const float bir = bi[j], biz = bi[HH+j], bin = bi[2*HH+j];
    const float bhr = bh[j], bhz = bh[HH+j], bhn = bh[2*HH+j];
    #pragma unroll
    for (int bl=0; bl<2; bl++){
        int b = b0 + ty*2 + bl;
        float giR = __fadd_rn(aI[bl][0], bir);
        float giZ = __fadd_rn(aI[bl][1], biz);
        float giN = __fadd_rn(aI[bl][2], bin);
        float ghR = __fadd_rn(aH[bl][0], bhr);
        float ghZ = __fadd_rn(aH[bl][1], bhz);
        float ghN = __fadd_rn(aH[bl][2], bhn);
        float r = xla_sigmoid(__fadd_rn(giR, ghR));
        float z = xla_sigmoid(__fadd_rn(giZ, ghZ));
        float n = xla_tanh(__fadd_rn(giN, __fmul_rn(r, ghN)));
        float hp = h_in[(size_t)b*HH + j];
        float hn = __fadd_rn(__fmul_rn(__fsub_rn(1.f,z),n), __fmul_rn(z,hp));
        h_out[(size_t)b*HH + j] = hn;
    }
}

// ---------------- per-row logsumexp + logp writeback + argmax(logp) -------
__global__ void softmax_k(float* __restrict__ out, int step)
{
    int b = blockIdx.x, tid = threadIdx.x;
    const float* row = g_logits + (size_t)b*VV;
    __shared__ float sv[256];
    __shared__ int   si[256];
    __shared__ double sd[256];
    float m = -3.4e38f;
    for (int k=tid;k<VV;k+=256) m = fmaxf(m, row[k]);
    sv[tid]=m; __syncthreads();
    for (int s=128;s>0;s>>=1){ if (tid<s) sv[tid]=fmaxf(sv[tid],sv[tid+s]); __syncthreads(); }
    float mx = sv[0];
    __syncthreads();
    float ps=0.f;
    double pd=0.0;
    int cnt=0;
    for (int k=tid;k<VV;k+=256){
        ps += expf(__fsub_rn(row[k], mx));
        if (++cnt==16){ pd += (double)ps; ps=0.f; cnt=0; }
    }
    pd += (double)ps;
    sd[tid]=pd; __syncthreads();
    for (int st=128;st>0;st>>=1){ if (tid<st) sd[tid]+=sd[tid+st]; __syncthreads(); }
    float lsh = logf((float)sd[0]);
    float* o = out + ((size_t)step*BB + b)*VV;
    float bm = -3.4e38f; int bi = VV;
    for (int k=tid;k<VV;k+=256){
        float v = __fsub_rn(__fsub_rn(row[k], mx), lsh);
        o[k] = v;
        if (v>bm || (v==bm && k<bi)){ bm=v; bi=k; }
    }
    sv[tid]=bm; si[tid]=bi; __syncthreads();
    for (int s=128;s>0;s>>=1){
        if (tid<s){
            float v2=sv[tid+s]; int i2=si[tid+s];
            if (v2>sv[tid] || (v2==sv[tid] && i2<si[tid])){ sv[tid]=v2; si[tid]=i2; }
        }
        __syncthreads();
    }
    if (tid==0) g_eid[b] = si[0];
}

// ---------------- rate head: sigmoid( relu([emb[eid],h]@W1^T+b1) @ W2^T + b2 )
__global__ void rate_head_k(const float* __restrict__ W1, const float* __restrict__ b1,
                            const float* __restrict__ W2, const float* __restrict__ b2,
                            const float* __restrict__ emb,
                            float* __restrict__ out_rate, int step,
                            const float* __restrict__ hcur)
{
    int b = blockIdx.x, tid = threadIdx.x;
    __shared__ float xc[EDIM+HH];
    __shared__ double red[256];
    int e = g_eid[b];
    if (tid < EDIM) xc[tid] = emb[(size_t)e*EDIM + tid];
    for (int k=tid;k<HH;k+=256) xc[EDIM+k] = hcur[(size_t)b*HH + k];
    __syncthreads();
    double partial = 0.0;
    for (int j=tid;j<HH;j+=256){
        const float* w = W1 + (size_t)j*(EDIM+HH);
        float acc = 0.f;
        #pragma unroll 8
        for (int k=0;k<EDIM+HH;k+=4){
            float4 wv = *(const float4*)(w+k);
            acc = fmaf(wv.x, xc[k],   acc);
            acc = fmaf(wv.y, xc[k+1], acc);
            acc = fmaf(wv.z, xc[k+2], acc);
            acc = fmaf(wv.w, xc[k+3], acc);
        }
        float pre = __fadd_rn(acc, b1[j]);
        partial += (double)__fmul_rn(fmaxf(pre, 0.f), W2[j]);
    }
    red[tid]=partial; __syncthreads();
    for (int s=128;s>0;s>>=1){ if (tid<s) red[tid]+=red[tid+s]; __syncthreads(); }
    if (tid==0){
        float y = __fadd_rn((float)red[0], b2[0]);
        float pr = xla_sigmoid(y);
        out_rate[step*BB + b] = pr;
        g_rate[b] = pr;
    }
}

// ---------------- init: zero step-0 outputs, h=0, seed decoder carry -------
__global__ void init_k(float* __restrict__ out, const int* __restrict__ trg_eid,
                       const float* __restrict__ trg_rate)
{
    long long i = (long long)blockIdx.x*blockDim.x + threadIdx.x;
    const long long RATE_OFF = (long long)TTRG*BB*VV;
    if (i < (long long)BB*VV) out[i] = 0.f;
    if (i < BB)               out[RATE_OFF + i] = 0.f;
    if (i < BB*HH)            g_h[i] = 0.f;
    if (i < BB){ g_eid[i] = trg_eid[i]; g_rate[i] = trg_rate[i]; }
}

// ---------------- launch -----------------------------------------------
extern "C" void kernel_launch(void* const* d_in, const int* in_sizes, int n_in,
                              void* d_out, int out_size)
{
    const float* src      = (const float*)d_in[0];
    const int*   src_len  = (const int*)  d_in[1];
    const int*   trg_eid  = (const int*)  d_in[2];
    const float* trg_rate = (const float*)d_in[3];
    const float* emb      = (const float*)d_in[4];
    const float* enc_Wi   = (const float*)d_in[5];
    const float* enc_Wh   = (const float*)d_in[6];
    const float* enc_bi   = (const float*)d_in[7];
    const float* enc_bh   = (const float*)d_in[8];
    const float* dec_Wi   = (const float*)d_in[9];
    const float* dec_Wh   = (const float*)d_in[10];
    const float* dec_bi   = (const float*)d_in[11];
    const float* dec_bh   = (const float*)d_in[12];
    const float* We       = (const float*)d_in[13];
    const float* be       = (const float*)d_in[14];
    const float* W1       = (const float*)d_in[15];
    const float* b1       = (const float*)d_in[16];
    const float* W2       = (const float*)d_in[17];
    const float* b2       = (const float*)d_in[18];
    float* out = (float*)d_out;

    float *p_h, *p_h2, *p_gi_enc;
    cudaGetSymbolAddress((void**)&p_h,      g_h);
    cudaGetSymbolAddress((void**)&p_h2,     g_h2);
    cudaGetSymbolAddress((void**)&p_gi_enc, g_gi_enc);
    float* p_logits;
    cudaGetSymbolAddress((void**)&p_logits, g_logits);

    float* hb[2] = {p_h, p_h2};
    int par = 0;

    init_k<<<10000,256>>>(out, trg_eid, trg_rate);

    // Encoder: precompute gi for all timesteps in one big parallel GEMM
    sgemm_k<64,64,32,4,4><<<dim3(G3H/64, (TSRC*BB)/64), dim3(16,16)>>>(
        src, INDIM, enc_Wi, enc_bi, p_gi_enc, TSRC*BB, G3H, INDIM);

    // Encoder recurrence (fused gh-GEMM + gate, masked semantics)
    for (int t=0;t<TSRC;t++){
        gru_enc_k<<<dim3(HH/32, BB/16), 256>>>(
            hb[par], hb[par^1], enc_Wh, enc_bh,
            p_gi_enc + (size_t)t*BB*G3H, src_len, t);
        par ^= 1;
    }

    // Decoder: greedy autoregressive
    for (int step=1; step<TTRG; step++){
        gru_dec_k<<<dim3(HH/32, BB/16), 256>>>(
            hb[par], hb[par^1], dec_Wi, dec_bi, dec_Wh, dec_bh, emb);
        par ^= 1;
        vgemm_k<<<(VV+127)/128, dim3(16,16)>>>(hb[par], We, be, p_logits);
        softmax_k<<<BB,256>>>(out, step);
        rate_head_k<<<BB,256>>>(W1, b1, W2, b2, emb,
                                out + (size_t)TTRG*BB*VV, step, hb[par]);
    }
}

// round 8
// speedup vs baseline: 2.3432x; 1.3229x over previous
#include <cuda_runtime.h>
#include <math.h>

#define BB   128      // batch
#define HH   512      // hidden
#define INDIM 256
#define EDIM 256
#define VV   20000
#define TSRC 64
#define TTRG 50
#define G3H  1536     // 3*H
#define KX   (EDIM+1) // 257
#define KSH  8        // split-K for K=512 (chunk 64)
#define KSI  4        // split-K for K=257 (chunk 65)

// ---------------- scratch (device globals; no allocation) ----------------
__device__ float g_h [BB*HH];
__device__ float g_h2[BB*HH];
__device__ float g_gi_enc[(size_t)TSRC*BB*G3H];   // 50.3 MB
__device__ float g_ph[(size_t)KSH*BB*G3H];        // gh partials 6.3 MB
__device__ float g_pi[(size_t)KSI*BB*G3H];        // gi partials 3.1 MB
__device__ float g_logits[(size_t)BB*VV];         // 10.24 MB
__device__ int   g_eid[BB];
__device__ float g_rate[BB];

// ---- XLA f32 tanh: Eigen-style rational approximation, no FMA fusion ----
__device__ __forceinline__ float xla_tanh(float x){
    float ax = fabsf(x);
    float xc = fmaxf(-7.90531110763549805f, fminf(7.90531110763549805f, x));
    float x2 = __fmul_rn(xc, xc);
    float np = -2.76076847742355e-16f;
    np = __fadd_rn(__fmul_rn(np, x2),  2.00018790482477e-13f);
    np = __fadd_rn(__fmul_rn(np, x2), -8.60467152213735e-11f);
    np = __fadd_rn(__fmul_rn(np, x2),  5.12229709037114e-08f);
    np = __fadd_rn(__fmul_rn(np, x2),  1.48572235717979e-05f);
    np = __fadd_rn(__fmul_rn(np, x2),  6.37261928875436e-04f);
    np = __fadd_rn(__fmul_rn(np, x2),  4.89352455891786e-03f);
    np = __fmul_rn(np, xc);
    float dp = 1.19825839466702e-06f;
    dp = __fadd_rn(__fmul_rn(dp, x2), 1.18534705686654e-04f);
    dp = __fadd_rn(__fmul_rn(dp, x2), 2.26843463243900e-03f);
    dp = __fadd_rn(__fmul_rn(dp, x2), 4.89352518554385e-03f);
    float r = __fdiv_rn(np, dp);
    return (ax < 0.0004f) ? x : r;
}
__device__ __forceinline__ float xla_sigmoid(float x){
    return __fadd_rn(0.5f, __fmul_rn(0.5f, xla_tanh(__fmul_rn(0.5f, x))));
}

// ---- packed f32x2 helpers (sm_103a FFMA2 path) ---------------------------
__device__ __forceinline__ unsigned long long packf2(float lo, float hi){
    unsigned long long r;
    asm("mov.b64 %0, {%1, %2};" : "=l"(r)
        : "r"(__float_as_uint(lo)), "r"(__float_as_uint(hi)));
    return r;
}
__device__ __forceinline__ void unpackf2(unsigned long long v, float& lo, float& hi){
    unsigned int a, b;
    asm("mov.b64 {%0, %1}, %2;" : "=r"(a), "=r"(b) : "l"(v));
    lo = __uint_as_float(a); hi = __uint_as_float(b);
}
__device__ __forceinline__ unsigned long long ffma2(
    unsigned long long a, unsigned long long b, unsigned long long c){
    unsigned long long d;
    asm("fma.rn.f32x2 %0, %1, %2, %3;" : "=l"(d) : "l"(a), "l"(b), "l"(c));
    return d;
}

// ---------------- plain SGEMM (encoder-Wi precompute only) ----------------
template<int BM,int BN,int BK,int TM,int TN>
__global__ void sgemm_k(const float* __restrict__ A, int lda,
                        const float* __restrict__ W,
                        const float* __restrict__ bias,
                        float* __restrict__ C,
                        int M, int N, int K)
{
    __shared__ float As[BK][BM+4];
    __shared__ float Ws[BK][BN+4];
    constexpr int NT = (BM/TM)*(BN/TN);
    const int tx = threadIdx.x;
    const int ty = threadIdx.y;
    const int tid = ty*(BN/TN)+tx;
    const int bm0 = blockIdx.y*BM;
    const int bn0 = blockIdx.x*BN;

    float acc[TM][TN];
    #pragma unroll
    for (int i=0;i<TM;i++)
        #pragma unroll
        for (int j=0;j<TN;j++) acc[i][j]=0.f;

    for (int k0=0;k0<K;k0+=BK){
        for (int i=tid;i<BM*BK;i+=NT){
            int kl=i%BK, ml=i/BK;
            int m=bm0+ml, kg=k0+kl;
            As[kl][ml] = (m<M && kg<K) ? A[(size_t)m*lda + kg] : 0.f;
        }
        for (int i=tid;i<BN*BK;i+=NT){
            int kl=i%BK, nl=i/BK;
            int n=bn0+nl, kg=k0+kl;
            Ws[kl][nl] = (n<N && kg<K) ? W[(size_t)n*K + kg] : 0.f;
        }
        __syncthreads();
        #pragma unroll
        for (int kk=0;kk<BK;kk++){
            float a[TM], b[TN];
            #pragma unroll
            for (int i=0;i<TM;i+=4){
                float4 v = *(const float4*)&As[kk][ty*TM+i];
                a[i]=v.x; a[i+1]=v.y; a[i+2]=v.z; a[i+3]=v.w;
            }
            #pragma unroll
            for (int j=0;j<TN;j+=4){
                float4 v = *(const float4*)&Ws[kk][tx*TN+j];
                b[j]=v.x; b[j+1]=v.y; b[j+2]=v.z; b[j+3]=v.w;
            }
            #pragma unroll
            for (int i=0;i<TM;i++)
                #pragma unroll
                for (int j=0;j<TN;j++)
                    acc[i][j] = fmaf(a[i], b[j], acc[i][j]);
        }
        __syncthreads();
    }
    #pragma unroll
    for (int i=0;i<TM;i++){
        int m=bm0+ty*TM+i;
        if (m>=M) continue;
        #pragma unroll
        for (int j=0;j<TN;j++){
            int n=bn0+tx*TN+j;
            if (n<N) C[(size_t)m*N+n] = __fadd_rn(acc[i][j], bias[n]);
        }
    }
}

// ---------------- split-K GRU GEMM: partials P[ks][b][G3H] ----------------
// gridDim.z slices: z<ksH -> gh path (A=h_in, W=Wh, K=512, chunk 64, ->ph)
//                   else  -> gi path (A=[emb[eid],rate], W=Wi, K=257, chunk 65, ->pi)
// Block: 32 b x 128 j, BK=32, 256 threads, thread tile 2b x 8j.
__global__ __launch_bounds__(256) void grugemm_k(
    const float* __restrict__ h_in,
    const float* __restrict__ Wh,
    const float* __restrict__ Wi,
    const float* __restrict__ emb,
    int ksH)
{
    __shared__ float As[32][36];
    __shared__ float Ws[32][132];
    __shared__ int   seid[32];
    __shared__ float srate[32];

    const int tid = threadIdx.x;
    const int tx  = tid & 15;     // j-group (8 j each)
    const int ty  = tid >> 4;     // b-pair  (2 b each)
    const int j0  = blockIdx.x*128;
    const int b0  = blockIdx.y*32;
    const int zi  = blockIdx.z;

    const bool isH = (zi < ksH);
    const int  K      = isH ? HH : KX;
    const int  chunk  = isH ? (HH/KSH) : 65;
    const int  ks     = isH ? zi : (zi - ksH);
    const float* W    = isH ? Wh : Wi;
    float* P          = isH ? g_ph : g_pi;
    const int  kbeg   = ks*chunk;
    const int  kend   = min(K, kbeg+chunk);

    if (!isH && tid < 32){
        seid[tid]  = g_eid[b0+tid];
        srate[tid] = g_rate[b0+tid];
    }
    if (!isH) __syncthreads();

    float acc[2][8];
    #pragma unroll
    for (int i=0;i<2;i++)
        #pragma unroll
        for (int j=0;j<8;j++) acc[i][j]=0.f;

    for (int k0=kbeg; k0<kend; k0+=32){
        // stage A tile: As[k][b]
        #pragma unroll
        for (int i=tid;i<32*32;i+=256){
            int bl=i>>5, kl=i&31;
            int kg=k0+kl;
            float v=0.f;
            if (kg<kend){
                if (isH) v = h_in[(size_t)(b0+bl)*HH + kg];
                else     v = (kg<EDIM) ? emb[(size_t)seid[bl]*EDIM + kg] : srate[bl];
            }
            As[kl][bl]=v;
        }
        // stage W tile: Ws[k][j]
        #pragma unroll
        for (int i=tid;i<128*32;i+=256){
            int jl=i>>5, kl=i&31;
            int kg=k0+kl;
            Ws[kl][jl] = (kg<kend) ? W[(size_t)(j0+jl)*K + kg] : 0.f;
        }
        __syncthreads();
        #pragma unroll
        for (int kk=0;kk<32;kk++){
            float2 a = *(const float2*)&As[kk][ty*2];
            float4 w0 = *(const float4*)&Ws[kk][tx*8];
            float4 w1 = *(const float4*)&Ws[kk][tx*8+4];
            acc[0][0]=fmaf(a.x,w0.x,acc[0][0]); acc[1][0]=fmaf(a.y,w0.x,acc[1][0]);
            acc[0][1]=fmaf(a.x,w0.y,acc[0][1]); acc[1][1]=fmaf(a.y,w0.y,acc[1][1]);
            acc[0][2]=fmaf(a.x,w0.z,acc[0][2]); acc[1][2]=fmaf(a.y,w0.z,acc[1][2]);
            acc[0][3]=fmaf(a.x,w0.w,acc[0][3]); acc[1][3]=fmaf(a.y,w0.w,acc[1][3]);
            acc[0][4]=fmaf(a.x,w1.x,acc[0][4]); acc[1][4]=fmaf(a.y,w1.x,acc[1][4]);
            acc[0][5]=fmaf(a.x,w1.y,acc[0][5]); acc[1][5]=fmaf(a.y,w1.y,acc[1][5]);
            acc[0][6]=fmaf(a.x,w1.z,acc[0][6]); acc[1][6]=fmaf(a.y,w1.z,acc[1][6]);
            acc[0][7]=fmaf(a.x,w1.w,acc[0][7]); acc[1][7]=fmaf(a.y,w1.w,acc[1][7]);
        }
        __syncthreads();
    }
    #pragma unroll
    for (int bl=0; bl<2; bl++){
        int b = b0 + ty*2 + bl;
        float* p = P + ((size_t)ks*BB + b)*G3H + j0 + tx*8;
        *(float4*)p       = make_float4(acc[bl][0],acc[bl][1],acc[bl][2],acc[bl][3]);
        *(float4*)(p+4)   = make_float4(acc[bl][4],acc[bl][5],acc[bl][6],acc[bl][7]);
    }
}

// ---------------- encoder gate: reduce ph partials + gate + mask ----------
__global__ __launch_bounds__(256) void gate_enc_k(
    const float* __restrict__ h_in, float* __restrict__ h_out,
    const float* __restrict__ bh,
    const float* __restrict__ gi_t,
    const int* __restrict__ src_len, int t)
{
    int idx = blockIdx.x*blockDim.x + threadIdx.x;
    if (idx >= BB*HH) return;
    int b = idx / HH, j = idx % HH;
    float gh[3];
    #pragma unroll
    for (int g=0; g<3; g++){
        float s = 0.f;
        #pragma unroll
        for (int ks=0; ks<KSH; ks++)
            s = __fadd_rn(s, g_ph[((size_t)ks*BB + b)*G3H + g*HH + j]);
        gh[g] = __fadd_rn(s, bh[g*HH+j]);
    }
    const float* gi = gi_t + (size_t)b*G3H;
    float r = xla_sigmoid(__fadd_rn(gi[j],      gh[0]));
    float z = xla_sigmoid(__fadd_rn(gi[HH+j],   gh[1]));
    float n = xla_tanh(__fadd_rn(gi[2*HH+j], __fmul_rn(r, gh[2])));
    float hp = h_in[idx];
    float hn = __fadd_rn(__fmul_rn(__fsub_rn(1.f,z),n), __fmul_rn(z,hp));
    if (t >= src_len[b]) hn = hp;
    h_out[idx] = hn;
}

// ---------------- decoder gate: reduce ph+pi partials + gate --------------
__global__ __launch_bounds__(256) void gate_dec_k(
    const float* __restrict__ h_in, float* __restrict__ h_out,
    const float* __restrict__ bi, const float* __restrict__ bh)
{
    int idx = blockIdx.x*blockDim.x + threadIdx.x;
    if (idx >= BB*HH) return;
    int b = idx / HH, j = idx % HH;
    float gh[3], gi[3];
    #pragma unroll
    for (int g=0; g<3; g++){
        float s = 0.f;
        #pragma unroll
        for (int ks=0; ks<KSH; ks++)
            s = __fadd_rn(s, g_ph[((size_t)ks*BB + b)*G3H + g*HH + j]);
        gh[g] = __fadd_rn(s, bh[g*HH+j]);
        float si = 0.f;
        #pragma unroll
        for (int ks=0; ks<KSI; ks++)
            si = __fadd_rn(si, g_pi[((size_t)ks*BB + b)*G3H + g*HH + j]);
        gi[g] = __fadd_rn(si, bi[g*HH+j]);
    }
    float r = xla_sigmoid(__fadd_rn(gi[0], gh[0]));
    float z = xla_sigmoid(__fadd_rn(gi[1], gh[1]));
    float n = xla_tanh(__fadd_rn(gi[2], __fmul_rn(r, gh[2])));
    float hp = h_in[idx];
    float hn = __fadd_rn(__fmul_rn(__fsub_rn(1.f,z),n), __fmul_rn(z,hp));
    h_out[idx] = hn;
}

// ---------------- vocab GEMM: logits[128,20000] = h @ We^T + be (FFMA2) ---
__global__ __launch_bounds__(256) void vgemm_k(const float* __restrict__ A,
                                               const float* __restrict__ W,
                                               const float* __restrict__ bias,
                                               float* __restrict__ C)
{
    __shared__ float As[32][132];
    __shared__ float Ws[32][132];
    const int tx = threadIdx.x;
    const int ty = threadIdx.y;
    const int tid = ty*16+tx;
    const int bn0 = blockIdx.x*128;

    unsigned long long acc2[8][4];
    #pragma unroll
    for (int i=0;i<8;i++)
        #pragma unroll
        for (int p=0;p<4;p++) acc2[i][p]=0ull;

    for (int k0=0;k0<HH;k0+=32){
        for (int i=tid;i<128*32;i+=256){
            int kl=i%32, ml=i/32;
            As[kl][ml] = A[(size_t)ml*HH + k0+kl];
        }
        for (int i=tid;i<128*32;i+=256){
            int kl=i%32, nl=i/32;
            int n=bn0+nl;
            Ws[kl][nl] = (n<VV) ? W[(size_t)n*HH + k0+kl] : 0.f;
        }
        __syncthreads();
        #pragma unroll
        for (int kk=0;kk<32;kk++){
            float4 a0 = *(const float4*)&As[kk][ty*8];
            float4 a1 = *(const float4*)&As[kk][ty*8+4];
            float4 b0 = *(const float4*)&Ws[kk][tx*8];
            float4 b1 = *(const float4*)&Ws[kk][tx*8+4];
            unsigned long long A2[8], B2[4];
            A2[0]=packf2(a0.x,a0.x); A2[1]=packf2(a0.y,a0.y);
            A2[2]=packf2(a0.z,a0.z); A2[3]=packf2(a0.w,a0.w);
            A2[4]=packf2(a1.x,a1.x); A2[5]=packf2(a1.y,a1.y);
            A2[6]=packf2(a1.z,a1.z); A2[7]=packf2(a1.w,a1.w);
            B2[0]=packf2(b0.x,b0.y); B2[1]=packf2(b0.z,b0.w);
            B2[2]=packf2(b1.x,b1.y); B2[3]=packf2(b1.z,b1.w);
            #pragma unroll
            for (int i=0;i<8;i++)
                #pragma unroll
                for (int p=0;p<4;p++)
                    acc2[i][p] = ffma2(A2[i], B2[p], acc2[i][p]);
        }
        __syncthreads();
    }
    #pragma unroll
    for (int i=0;i<8;i++){
        int m = ty*8+i;
        #pragma unroll
        for (int p=0;p<4;p++){
            float lo, hi;
            unpackf2(acc2[i][p], lo, hi);
            int n0 = bn0 + tx*8 + p*2;
            if (n0   < VV) C[(size_t)m*VV + n0  ] = __fadd_rn(lo, bias[n0  ]);
            if (n0+1 < VV) C[(size_t)m*VV + n0+1] = __fadd_rn(hi, bias[n0+1]);
        }
    }
}

// ---------------- per-row logsumexp + logp writeback + argmax(logp) -------
__global__ void softmax_k(float* __restrict__ out, int step)
{
    int b = blockIdx.x, tid = threadIdx.x;
    const float* row = g_logits + (size_t)b*VV;
    __shared__ float sv[256];
    __shared__ int   si[256];
    __shared__ double sd[256];
    float m = -3.4e38f;
    for (int k=tid;k<VV;k+=256) m = fmaxf(m, row[k]);
    sv[tid]=m; __syncthreads();
    for (int s=128;s>0;s>>=1){ if (tid<s) sv[tid]=fmaxf(sv[tid],sv[tid+s]); __syncthreads(); }
    float mx = sv[0];
    __syncthreads();
    float ps=0.f;
    double pd=0.0;
    int cnt=0;
    for (int k=tid;k<VV;k+=256){
        ps += expf(__fsub_rn(row[k], mx));
        if (++cnt==16){ pd += (double)ps; ps=0.f; cnt=0; }
    }
    pd += (double)ps;
    sd[tid]=pd; __syncthreads();
    for (int st=128;st>0;st>>=1){ if (tid<st) sd[tid]+=sd[tid+st]; __syncthreads(); }
    float lsh = logf((float)sd[0]);
    float* o = out + ((size_t)step*BB + b)*VV;
    float bm = -3.4e38f; int bi = VV;
    for (int k=tid;k<VV;k+=256){
        float v = __fsub_rn(__fsub_rn(row[k], mx), lsh);
        o[k] = v;
        if (v>bm || (v==bm && k<bi)){ bm=v; bi=k; }
    }
    sv[tid]=bm; si[tid]=bi; __syncthreads();
    for (int s=128;s>0;s>>=1){
        if (tid<s){
            float v2=sv[tid+s]; int i2=si[tid+s];
            if (v2>sv[tid] || (v2==sv[tid] && i2<si[tid])){ sv[tid]=v2; si[tid]=i2; }
        }
        __syncthreads();
    }
    if (tid==0) g_eid[b] = si[0];
}

// ---------------- rate head: sigmoid( relu([emb[eid],h]@W1^T+b1) @ W2^T + b2 )
__global__ void rate_head_k(const float* __restrict__ W1, const float* __restrict__ b1,
                            const float* __restrict__ W2, const float* __restrict__ b2,
                            const float* __restrict__ emb,
                            float* __restrict__ out_rate, int step,
                            const float* __restrict__ hcur)
{
    int b = blockIdx.x, tid = threadIdx.x;
    __shared__ float xc[EDIM+HH];
    __shared__ double red[256];
    int e = g_eid[b];
    if (tid < EDIM) xc[tid] = emb[(size_t)e*EDIM + tid];
    for (int k=tid;k<HH;k+=256) xc[EDIM+k] = hcur[(size_t)b*HH + k];
    __syncthreads();
    double partial = 0.0;
    for (int j=tid;j<HH;j+=256){
        const float* w = W1 + (size_t)j*(EDIM+HH);
        float acc = 0.f;
        #pragma unroll 8
        for (int k=0;k<EDIM+HH;k+=4){
            float4 wv = *(const float4*)(w+k);
            acc = fmaf(wv.x, xc[k],   acc);
            acc = fmaf(wv.y, xc[k+1], acc);
            acc = fmaf(wv.z, xc[k+2], acc);
            acc = fmaf(wv.w, xc[k+3], acc);
        }
        float pre = __fadd_rn(acc, b1[j]);
        partial += (double)__fmul_rn(fmaxf(pre, 0.f), W2[j]);
    }
    red[tid]=partial; __syncthreads();
    for (int s=128;s>0;s>>=1){ if (tid<s) red[tid]+=red[tid+s]; __syncthreads(); }
    if (tid==0){
        float y = __fadd_rn((float)red[0], b2[0]);
        float pr = xla_sigmoid(y);
        out_rate[step*BB + b] = pr;
        g_rate[b] = pr;
    }
}

// ---------------- init: zero step-0 outputs, h=0, seed decoder carry -------
__global__ void init_k(float* __restrict__ out, const int* __restrict__ trg_eid,
                       const float* __restrict__ trg_rate)
{
    long long i = (long long)blockIdx.x*blockDim.x + threadIdx.x;
    const long long RATE_OFF = (long long)TTRG*BB*VV;
    if (i < (long long)BB*VV) out[i] = 0.f;
    if (i < BB)               out[RATE_OFF + i] = 0.f;
    if (i < BB*HH)            g_h[i] = 0.f;
    if (i < BB){ g_eid[i] = trg_eid[i]; g_rate[i] = trg_rate[i]; }
}

// ---------------- launch -----------------------------------------------
extern "C" void kernel_launch(void* const* d_in, const int* in_sizes, int n_in,
                              void* d_out, int out_size)
{
    const float* src      = (const float*)d_in[0];
    const int*   src_len  = (const int*)  d_in[1];
    const int*   trg_eid  = (const int*)  d_in[2];
    const float* trg_rate = (const float*)d_in[3];
    const float* emb      = (const float*)d_in[4];
    const float* enc_Wi   = (const float*)d_in[5];
    const float* enc_Wh   = (const float*)d_in[6];
    const float* enc_bi   = (const float*)d_in[7];
    const float* enc_bh   = (const float*)d_in[8];
    const float* dec_Wi   = (const float*)d_in[9];
    const float* dec_Wh   = (const float*)d_in[10];
    const float* dec_bi   = (const float*)d_in[11];
    const float* dec_bh   = (const float*)d_in[12];
    const float* We       = (const float*)d_in[13];
    const float* be       = (const float*)d_in[14];
    const float* W1       = (const float*)d_in[15];
    const float* b1       = (const float*)d_in[16];
    const float* W2       = (const float*)d_in[17];
    const float* b2       = (const float*)d_in[18];
    float* out = (float*)d_out;

    float *p_h, *p_h2, *p_gi_enc, *p_logits;
    cudaGetSymbolAddress((void**)&p_h,      g_h);
    cudaGetSymbolAddress((void**)&p_h2,     g_h2);
    cudaGetSymbolAddress((void**)&p_gi_enc, g_gi_enc);
    cudaGetSymbolAddress((void**)&p_logits, g_logits);

    float* hb[2] = {p_h, p_h2};
    int par = 0;

    init_k<<<10000,256>>>(out, trg_eid, trg_rate);

    // Encoder: precompute gi for all timesteps in one big parallel GEMM
    sgemm_k<64,64,32,4,4><<<dim3(G3H/64, (TSRC*BB)/64), dim3(16,16)>>>(
        src, INDIM, enc_Wi, enc_bi, p_gi_enc, TSRC*BB, G3H, INDIM);

    // Encoder recurrence: split-K gh GEMM + gate
    for (int t=0;t<TSRC;t++){
        grugemm_k<<<dim3(G3H/128, BB/32, KSH), 256>>>(
            hb[par], enc_Wh, nullptr, emb, KSH);
        gate_enc_k<<<(BB*HH)/256, 256>>>(
            hb[par], hb[par^1], enc_bh,
            p_gi_enc + (size_t)t*BB*G3H, src_len, t);
        par ^= 1;
    }

    // Decoder: greedy autoregressive
    for (int step=1; step<TTRG; step++){
        grugemm_k<<<dim3(G3H/128, BB/32, KSH+KSI), 256>>>(
            hb[par], dec_Wh, dec_Wi, emb, KSH);
        gate_dec_k<<<(BB*HH)/256, 256>>>(
            hb[par], hb[par^1], dec_bi, dec_bh);
        par ^= 1;
        vgemm_k<<<(VV+127)/128, dim3(16,16)>>>(hb[par], We, be, p_logits);
        softmax_k<<<BB,256>>>(out, step);
        rate_head_k<<<BB,256>>>(W1, b1, W2, b2, emb,
                                out + (size_t)TTRG*BB*VV, step, hb[par]);
    }
}